// round 14
// baseline (speedup 1.0000x reference)
#include <cuda_runtime.h>
#include <cuda_bf16.h>
#include <cstdint>

// Problem constants (fixed by the reference).
#define N_ENT   50000
#define N_REL   16
#define N_BASES 8
#define H_DIM   128
#define N_EDGES 800000

// ---------------------------------------------------------------------------
// Device scratch (allocation-free rule: __device__ globals).
// ---------------------------------------------------------------------------
__device__ __nv_bfloat16 g_Wt_hi[9 * H_DIM * H_DIM];   // [g][o][i]
__device__ __nv_bfloat16 g_Wt_lo[9 * H_DIM * H_DIM];
__device__ __nv_bfloat16 g_A_hi[(size_t)N_ENT * H_DIM];
__device__ __nv_bfloat16 g_A_lo[(size_t)N_ENT * H_DIM];
__device__ __nv_bfloat16 g_comp_hi[(size_t)N_BASES * N_ENT * H_DIM];
__device__ __nv_bfloat16 g_comp_lo[(size_t)N_BASES * N_ENT * H_DIM];
__device__ float         g_H1[(size_t)N_ENT * H_DIM];
__device__ int           g_cnt[N_ENT];
__device__ int           g_off[N_ENT + 1];
__device__ int           g_cur[N_ENT];
__device__ uint32_t      g_pay[N_EDGES];   // (rel<<16) | src, grouped by dst

// ---------------------------------------------------------------------------
// helpers
// ---------------------------------------------------------------------------
__device__ __forceinline__ uint32_t smem_u32(const void* p) {
    uint32_t a;
    asm("{ .reg .u64 t; cvta.to.shared.u64 t, %1; cvt.u32.u64 %0, t; }"
        : "=r"(a) : "l"(p));
    return a;
}

#define LDMX4(r0, r1, r2, r3, addr)                                           \
    asm volatile("ldmatrix.sync.aligned.m8n8.x4.shared.b16 {%0,%1,%2,%3}, [%4];" \
                 : "=r"(r0), "=r"(r1), "=r"(r2), "=r"(r3) : "r"(addr))

#define MMA_BF16(C, A, B)                                                     \
    asm volatile(                                                             \
        "mma.sync.aligned.m16n8k16.row.col.f32.bf16.bf16.f32 "                \
        "{%0,%1,%2,%3}, {%4,%5,%6,%7}, {%8,%9}, {%0,%1,%2,%3};"               \
        : "+f"((C)[0]), "+f"((C)[1]), "+f"((C)[2]), "+f"((C)[3])              \
        : "r"((A)[0]), "r"((A)[1]), "r"((A)[2]), "r"((A)[3]),                 \
          "r"((B)[0]), "r"((B)[1]))

#define CP_ASYNC16(dst, src)                                                  \
    asm volatile("cp.async.cg.shared.global [%0], [%1], 16;"                  \
                 :: "r"(dst), "l"(src))
#define CP_COMMIT()  asm volatile("cp.async.commit_group;" ::: "memory")
#define CP_WAIT0()   asm volatile("cp.async.wait_group 0;" ::: "memory")

// packed fp32x2 (sm_103a FFMA2 path — only reachable via PTX f32x2)
#define FMA_F32X2(d, a, b, c)                                                 \
    asm("fma.rn.f32x2 %0, %1, %2, %3;" : "=l"(d) : "l"(a), "l"(b), "l"(c))
#define PACK_F32X2(out, lo, hi)                                               \
    asm("mov.b64 %0, {%1, %2};" : "=l"(out) : "r"(lo), "r"(hi))
#define UNPACK_F32X2(lo, hi, in)                                              \
    asm("mov.b64 {%0, %1}, %2;" : "=r"(lo), "=r"(hi) : "l"(in))

__device__ __forceinline__ uint32_t bf2x(float a, float b) {
    __nv_bfloat162 t(__float2bfloat16(a), __float2bfloat16(b));
    return *(uint32_t*)&t;
}

// ---------------------------------------------------------------------------
// Edge binning by dst. hist expects cnt==0 (static-zero first call; scan
// re-zeroes for subsequent graph replays).
// ---------------------------------------------------------------------------
__global__ void hist_kernel(const int* __restrict__ dst,
                            int* __restrict__ cnt, int E)
{
    int e = blockIdx.x * blockDim.x + threadIdx.x;
    if (e >= E) return;
    atomicAdd(&cnt[dst[e]], 1);
}

__global__ __launch_bounds__(1024)
void scan_kernel(int* __restrict__ cnt,
                 int* __restrict__ off, int* __restrict__ cur)
{
    __shared__ int ps[1024];
    const int t = threadIdx.x;
    const int CH = (N_ENT + 1023) / 1024;
    const int lo = t * CH;
    const int hi = min(lo + CH, N_ENT);
    int s = 0;
    for (int i = lo; i < hi; i++) s += cnt[i];
    ps[t] = s;
    __syncthreads();
    for (int d = 1; d < 1024; d <<= 1) {
        int v = (t >= d) ? ps[t - d] : 0;
        __syncthreads();
        ps[t] += v;
        __syncthreads();
    }
    int run = ps[t] - s;
    for (int i = lo; i < hi; i++) {
        off[i] = run;
        cur[i] = run;
        run += cnt[i];
        cnt[i] = 0;
    }
    if (t == 1023) off[N_ENT] = run;
}

__global__ void fill_kernel(const int* __restrict__ src,
                            const int* __restrict__ dst,
                            const int* __restrict__ rel,
                            int* __restrict__ cur,
                            uint32_t* __restrict__ pay, int E)
{
    int e = blockIdx.x * blockDim.x + threadIdx.x;
    if (e >= E) return;
    int pos = atomicAdd(&cur[dst[e]], 1);
    pay[pos] = ((uint32_t)rel[e] << 16) | (uint32_t)src[e];
}

// ---------------------------------------------------------------------------
// Aggregate (f32x2 packed): warp per dst node.
// compact[n,b] = sum_edges w_comp[rel,b]*h[src]; fp32 accum, no atomics.
// Per edge per lane: 1 LDG.128 + 4 LDS.128 (packed wc pairs) + 2 packs
// + 16 FFMA2 (vs 32 scalar FFMA before).
// ---------------------------------------------------------------------------
__global__ __launch_bounds__(256)
void agg_kernel(const float* __restrict__ h,
                const uint32_t* __restrict__ pay,
                const int* __restrict__ off,
                const float* __restrict__ w_comp,
                __nv_bfloat16* __restrict__ comp_hi,
                __nv_bfloat16* __restrict__ comp_lo,
                int relu)
{
    __shared__ unsigned long long wc2[N_REL][N_BASES];   // duplicated pairs
    const int tid = threadIdx.x;
    if (tid < N_REL * N_BASES) {
        uint32_t u = __float_as_uint(w_comp[tid]);
        unsigned long long p;
        PACK_F32X2(p, u, u);
        wc2[tid >> 3][tid & 7] = p;
    }
    __syncthreads();

    const int w    = (blockIdx.x * blockDim.x + tid) >> 5;
    const int lane = tid & 31;
    if (w >= N_ENT) return;

    const int o0 = off[w];
    const int n  = off[w + 1] - o0;

    unsigned long long cb2[N_BASES][2];
    {
        unsigned long long z;
        PACK_F32X2(z, 0u, 0u);
#pragma unroll
        for (int b = 0; b < N_BASES; b++) { cb2[b][0] = z; cb2[b][1] = z; }
    }

    const uint32_t wcbase = smem_u32(&wc2[0][0]);

    for (int e = 0; e < n; e++) {
        uint32_t p = pay[o0 + e];
        int r = (int)(p >> 16);
        int s = (int)(p & 0xFFFFu);
        float4 v = *(const float4*)(h + (size_t)s * H_DIM + lane * 4);
        if (relu) {
            v.x = fmaxf(v.x, 0.f); v.y = fmaxf(v.y, 0.f);
            v.z = fmaxf(v.z, 0.f); v.w = fmaxf(v.w, 0.f);
        }
        unsigned long long vxy, vzw;
        PACK_F32X2(vxy, __float_as_uint(v.x), __float_as_uint(v.y));
        PACK_F32X2(vzw, __float_as_uint(v.z), __float_as_uint(v.w));

        const uint32_t wrow = wcbase + (uint32_t)r * (N_BASES * 8);
#pragma unroll
        for (int bp = 0; bp < 4; bp++) {          // 2 bases per v2.u64 load
            unsigned long long w0, w1;
            asm("ld.shared.v2.u64 {%0,%1}, [%2];"
                : "=l"(w0), "=l"(w1) : "r"(wrow + bp * 16));
            FMA_F32X2(cb2[2 * bp][0],     w0, vxy, cb2[2 * bp][0]);
            FMA_F32X2(cb2[2 * bp][1],     w0, vzw, cb2[2 * bp][1]);
            FMA_F32X2(cb2[2 * bp + 1][0], w1, vxy, cb2[2 * bp + 1][0]);
            FMA_F32X2(cb2[2 * bp + 1][1], w1, vzw, cb2[2 * bp + 1][1]);
        }
    }

#pragma unroll
    for (int b = 0; b < N_BASES; b++) {
        size_t base = ((size_t)b * N_ENT + w) * H_DIM + lane * 4;
        float c[4];
        {
            uint32_t u0, u1, u2, u3;
            UNPACK_F32X2(u0, u1, cb2[b][0]);
            UNPACK_F32X2(u2, u3, cb2[b][1]);
            c[0] = __uint_as_float(u0); c[1] = __uint_as_float(u1);
            c[2] = __uint_as_float(u2); c[3] = __uint_as_float(u3);
        }
        float hi[4], lo[4];
#pragma unroll
        for (int k = 0; k < 4; k++) {
            hi[k] = __bfloat162float(__float2bfloat16(c[k]));
            lo[k] = c[k] - hi[k];
        }
        uint2 uh, ul;
        uh.x = bf2x(hi[0], hi[1]); uh.y = bf2x(hi[2], hi[3]);
        ul.x = bf2x(lo[0], lo[1]); ul.y = bf2x(lo[2], lo[3]);
        *(uint2*)(comp_hi + base) = uh;
        *(uint2*)(comp_lo + base) = ul;
    }
}

// ---------------------------------------------------------------------------
// Prep W planes: g<8 -> basis[g] transposed [o][i]; g==8 -> loop_w transposed.
// ---------------------------------------------------------------------------
__global__ void prep_w_kernel(const float* __restrict__ basis,
                              const float* __restrict__ loop_w,
                              __nv_bfloat16* __restrict__ Wt_hi,
                              __nv_bfloat16* __restrict__ Wt_lo)
{
    int idx = blockIdx.x * blockDim.x + threadIdx.x;
    const int total = 9 * H_DIM * H_DIM;
    if (idx >= total) return;
    int g  = idx >> 14;
    int io = idx & 16383;                  // i*128 + o
    float s = (g < 8) ? basis[g * 16384 + io] : loop_w[io];
    int i = io >> 7, o = io & 127;
    size_t oidx = (size_t)g * 16384 + o * 128 + i;
    __nv_bfloat16 hi = __float2bfloat16(s);
    __nv_bfloat16 lo = __float2bfloat16(s - __bfloat162float(hi));
    Wt_hi[oidx] = hi;
    Wt_lo[oidx] = lo;
}

// ---------------------------------------------------------------------------
// Split input activations fp32 -> bf16 hi/lo (optional fused ReLU).
// ---------------------------------------------------------------------------
__global__ void split_kernel(const float* __restrict__ x,
                             __nv_bfloat16* __restrict__ hi,
                             __nv_bfloat16* __restrict__ lo,
                             int n4, int relu)
{
    int i = blockIdx.x * blockDim.x + threadIdx.x;
    if (i >= n4) return;
    float4 v = ((const float4*)x)[i];
    if (relu) {
        v.x = fmaxf(v.x, 0.f); v.y = fmaxf(v.y, 0.f);
        v.z = fmaxf(v.z, 0.f); v.w = fmaxf(v.w, 0.f);
    }
    float e[4] = {v.x, v.y, v.z, v.w};
    __nv_bfloat16 h[4], l[4];
#pragma unroll
    for (int j = 0; j < 4; j++) {
        h[j] = __float2bfloat16(e[j]);
        l[j] = __float2bfloat16(e[j] - __bfloat162float(h[j]));
    }
    ((__nv_bfloat162*)hi)[2 * i]     = __nv_bfloat162(h[0], h[1]);
    ((__nv_bfloat162*)hi)[2 * i + 1] = __nv_bfloat162(h[2], h[3]);
    ((__nv_bfloat162*)lo)[2 * i]     = __nv_bfloat162(l[0], l[1]);
    ((__nv_bfloat162*)lo)[2 * i + 1] = __nv_bfloat162(l[2], l[3]);
}

// ---------------------------------------------------------------------------
// Single K=1152 GEMM: OUT = [compact_0..7 | h] @ [[basis_0..7];[loop]] + bias.
// CTA tile 128x128, 8 warps (4M x 2N), warp tile 32x64, 3-term bf16 split,
// fp32 acc across whole K, double-buffered cp.async stages. Optional fused
// ReLU on the output (final layer).
// ---------------------------------------------------------------------------
#define PITCH9   144
#define ST_A_HI  0
#define ST_A_LO  18432
#define ST_W_HI  36864
#define ST_W_LO  55296
#define STAGE_SZ 73728
#define GEMM_SMEM (2 * STAGE_SZ)        // 147456

__global__ __launch_bounds__(256, 1)
void gemm9_kernel(const __nv_bfloat16* __restrict__ comp_hi,
                  const __nv_bfloat16* __restrict__ comp_lo,
                  const __nv_bfloat16* __restrict__ Ahi,
                  const __nv_bfloat16* __restrict__ Alo,
                  const __nv_bfloat16* __restrict__ Wthi,
                  const __nv_bfloat16* __restrict__ Wtlo,
                  const float* __restrict__ bias,
                  float* __restrict__ OUT,
                  int M, int relu)
{
    extern __shared__ char smem[];
    const uint32_t sb = smem_u32(smem);
    const int tid   = threadIdx.x;
    const int wid   = tid >> 5;
    const int lane  = tid & 31;
    const int wm    = wid >> 1;
    const int wn    = wid & 1;
    const int m0    = blockIdx.x * 128;

    const int q   = lane >> 3;
    const int r8  = lane & 7;
    const int arow_base = wm * 32 + r8 + (q & 1) * 8;
    const int acol_add  = (q >> 1) * 8;
    const int brow_base = wn * 64 + (q >> 1) * 8 + r8;
    const int bcol_add  = (q & 1) * 8;
    const int gr0 = m0 + wm * 32 + (lane >> 2);

#define PREFETCH(t)                                                           \
    do {                                                                      \
        const int _g = (t) >> 1, _hf = (t) & 1;                               \
        const __nv_bfloat16* _ah = (_g < 8)                                   \
            ? comp_hi + (size_t)_g * N_ENT * H_DIM : Ahi;                     \
        const __nv_bfloat16* _al = (_g < 8)                                   \
            ? comp_lo + (size_t)_g * N_ENT * H_DIM : Alo;                     \
        const __nv_bfloat16* _wh = Wthi + _g * 16384;                         \
        const __nv_bfloat16* _wl = Wtlo + _g * 16384;                         \
        const uint32_t _st = sb + ((t) & 1) * STAGE_SZ;                       \
        _Pragma("unroll")                                                     \
        for (int _i = 0; _i < 4; _i++) {                                      \
            int _idx = tid + _i * 256;                                        \
            int _row = _idx >> 3;                                             \
            int _c8  = (_idx & 7) * 8;                                        \
            uint32_t _sa = _st + _row * PITCH9 + _c8 * 2;                     \
            if (m0 + _row < M) {                                              \
                CP_ASYNC16(_sa + ST_A_HI,                                     \
                    _ah + (size_t)(m0 + _row) * H_DIM + _hf * 64 + _c8);      \
                CP_ASYNC16(_sa + ST_A_LO,                                     \
                    _al + (size_t)(m0 + _row) * H_DIM + _hf * 64 + _c8);      \
            } else {                                                          \
                *(uint4*)(smem + (_sa + ST_A_HI - sb)) = make_uint4(0,0,0,0); \
                *(uint4*)(smem + (_sa + ST_A_LO - sb)) = make_uint4(0,0,0,0); \
            }                                                                 \
            CP_ASYNC16(_sa + ST_W_HI,                                         \
                _wh + (size_t)_row * H_DIM + _hf * 64 + _c8);                 \
            CP_ASYNC16(_sa + ST_W_LO,                                         \
                _wl + (size_t)_row * H_DIM + _hf * 64 + _c8);                 \
        }                                                                     \
    } while (0)

    float acc[2][8][4];
#pragma unroll
    for (int mt = 0; mt < 2; mt++)
#pragma unroll
        for (int nt = 0; nt < 8; nt++)
#pragma unroll
            for (int c = 0; c < 4; c++) acc[mt][nt][c] = 0.f;

    PREFETCH(0);
    CP_COMMIT();

    for (int t = 0; t < 18; t++) {
        CP_WAIT0();
        __syncthreads();

        if (t < 17) {
            PREFETCH(t + 1);
            CP_COMMIT();
        }

        const uint32_t st = sb + (t & 1) * STAGE_SZ;

#pragma unroll
        for (int ks = 0; ks < 4; ks++) {
            const int k0 = ks * 16;
            uint32_t ah[2][4], al[2][4], bh[8][2], bl[8][2];
#pragma unroll
            for (int mt = 0; mt < 2; mt++) {
                uint32_t off = (uint32_t)((arow_base + mt * 16) * PITCH9
                                          + (k0 + acol_add) * 2);
                LDMX4(ah[mt][0], ah[mt][1], ah[mt][2], ah[mt][3],
                      st + ST_A_HI + off);
                LDMX4(al[mt][0], al[mt][1], al[mt][2], al[mt][3],
                      st + ST_A_LO + off);
            }
#pragma unroll
            for (int p = 0; p < 4; p++) {
                uint32_t off = (uint32_t)((brow_base + p * 16) * PITCH9
                                          + (k0 + bcol_add) * 2);
                LDMX4(bh[2 * p][0], bh[2 * p][1], bh[2 * p + 1][0],
                      bh[2 * p + 1][1], st + ST_W_HI + off);
                LDMX4(bl[2 * p][0], bl[2 * p][1], bl[2 * p + 1][0],
                      bl[2 * p + 1][1], st + ST_W_LO + off);
            }
#pragma unroll
            for (int mt = 0; mt < 2; mt++)
#pragma unroll
                for (int nt = 0; nt < 8; nt++) {
                    MMA_BF16(acc[mt][nt], ah[mt], bh[nt]);
                    MMA_BF16(acc[mt][nt], ah[mt], bl[nt]);
                    MMA_BF16(acc[mt][nt], al[mt], bh[nt]);
                }
        }
        __syncthreads();
    }

    // ---- epilogue: OUT = acc + bias (optional ReLU) ----
#pragma unroll
    for (int mt = 0; mt < 2; mt++) {
        int row = gr0 + mt * 16;
#pragma unroll
        for (int nt = 0; nt < 8; nt++) {
            int col = wn * 64 + nt * 8 + (lane & 3) * 2;
            float2 bv = *(const float2*)(bias + col);
            float o0 = acc[mt][nt][0] + bv.x, o1 = acc[mt][nt][1] + bv.y;
            float o2 = acc[mt][nt][2] + bv.x, o3 = acc[mt][nt][3] + bv.y;
            if (relu) {
                o0 = fmaxf(o0, 0.f); o1 = fmaxf(o1, 0.f);
                o2 = fmaxf(o2, 0.f); o3 = fmaxf(o3, 0.f);
            }
            if (row < M)
                *(float2*)(OUT + (size_t)row * H_DIM + col) = make_float2(o0, o1);
            if (row + 8 < M)
                *(float2*)(OUT + (size_t)(row + 8) * H_DIM + col) = make_float2(o2, o3);
        }
    }
#undef PREFETCH
}

// ---------------------------------------------------------------------------
// Launch. agg1 is the 4th launch -> ncu-profiled.
// ---------------------------------------------------------------------------
extern "C" void kernel_launch(void* const* d_in, const int* in_sizes, int n_in,
                              void* d_out, int out_size)
{
    const float* entity_emb = (const float*)d_in[0];
    const float* basis1     = (const float*)d_in[1];
    const float* w_comp1    = (const float*)d_in[2];
    const float* loop_w1    = (const float*)d_in[3];
    const float* bias1      = (const float*)d_in[4];
    const float* basis2     = (const float*)d_in[5];
    const float* w_comp2    = (const float*)d_in[6];
    const float* loop_w2    = (const float*)d_in[7];
    const float* bias2      = (const float*)d_in[8];
    const int*   src        = (const int*)d_in[9];
    const int*   dst        = (const int*)d_in[10];
    const int*   rel        = (const int*)d_in[11];
    float*       out        = (float*)d_out;

    const int E = in_sizes[9];

    __nv_bfloat16 *dWth, *dWtl, *dAh, *dAl, *dCh, *dCl;
    float *dH1;
    int *dcnt, *doff, *dcur;
    uint32_t *dpay;
    cudaGetSymbolAddress((void**)&dWth, g_Wt_hi);
    cudaGetSymbolAddress((void**)&dWtl, g_Wt_lo);
    cudaGetSymbolAddress((void**)&dAh,  g_A_hi);
    cudaGetSymbolAddress((void**)&dAl,  g_A_lo);
    cudaGetSymbolAddress((void**)&dCh,  g_comp_hi);
    cudaGetSymbolAddress((void**)&dCl,  g_comp_lo);
    cudaGetSymbolAddress((void**)&dH1,  g_H1);
    cudaGetSymbolAddress((void**)&dcnt, g_cnt);
    cudaGetSymbolAddress((void**)&doff, g_off);
    cudaGetSymbolAddress((void**)&dcur, g_cur);
    cudaGetSymbolAddress((void**)&dpay, g_pay);

    cudaFuncSetAttribute(gemm9_kernel,
                         cudaFuncAttributeMaxDynamicSharedMemorySize, GEMM_SMEM);

    const int pw_blocks = (9 * H_DIM * H_DIM + 255) / 256;
    const int n4        = N_ENT * H_DIM / 4;
    const int sp_blocks = (n4 + 255) / 256;
    const int eg_blocks = (E + 255) / 256;
    const int gemm_grid = (N_ENT + 127) / 128;       // 391
    const int agg_blocks = (N_ENT * 32 + 255) / 256;

    // ---------------- binning (cnt pre-zeroed; scan re-zeroes) ----------------
    hist_kernel<<<eg_blocks, 256>>>(dst, dcnt, E);
    scan_kernel<<<1, 1024>>>(dcnt, doff, dcur);
    fill_kernel<<<eg_blocks, 256>>>(src, dst, rel, dcur, dpay, E);

    // ---------------- Layer 1 ----------------
    agg_kernel<<<agg_blocks, 256>>>(entity_emb, dpay, doff, w_comp1,
                                    dCh, dCl, 0);              // profiled (#4)
    prep_w_kernel<<<pw_blocks, 256>>>(basis1, loop_w1, dWth, dWtl);
    split_kernel<<<sp_blocks, 256>>>(entity_emb, dAh, dAl, n4, 0);
    gemm9_kernel<<<gemm_grid, 256, GEMM_SMEM>>>(dCh, dCl, dAh, dAl,
                                                dWth, dWtl, bias1, dH1,
                                                N_ENT, 0);

    // ---------------- Layer 2 ----------------
    agg_kernel<<<agg_blocks, 256>>>(dH1, dpay, doff, w_comp2,
                                    dCh, dCl, 1);              // fused ReLU
    prep_w_kernel<<<pw_blocks, 256>>>(basis2, loop_w2, dWth, dWtl);
    split_kernel<<<sp_blocks, 256>>>(dH1, dAh, dAl, n4, 1);    // fused ReLU
    gemm9_kernel<<<gemm_grid, 256, GEMM_SMEM>>>(dCh, dCl, dAh, dAl,
                                                dWth, dWtl, bias2, out,
                                                N_ENT, 1);     // fused ReLU
}

// round 15
// speedup vs baseline: 1.5327x; 1.5327x over previous
#include <cuda_runtime.h>
#include <cuda_bf16.h>
#include <cstdint>

// Problem constants (fixed by the reference).
#define N_ENT   50000
#define N_REL   16
#define N_BASES 8
#define H_DIM   128
#define N_EDGES 800000

// ---------------------------------------------------------------------------
// Device scratch (allocation-free rule: __device__ globals).
// ---------------------------------------------------------------------------
__device__ __nv_bfloat16 g_Wt_hi[9 * H_DIM * H_DIM];   // [g][o][i]
__device__ __nv_bfloat16 g_Wt_lo[9 * H_DIM * H_DIM];
__device__ __nv_bfloat16 g_A_hi[(size_t)N_ENT * H_DIM];
__device__ __nv_bfloat16 g_A_lo[(size_t)N_ENT * H_DIM];
__device__ __nv_bfloat16 g_comp_hi[(size_t)N_BASES * N_ENT * H_DIM];
__device__ __nv_bfloat16 g_comp_lo[(size_t)N_BASES * N_ENT * H_DIM];
__device__ float         g_H1[(size_t)N_ENT * H_DIM];
__device__ int           g_cnt[N_ENT];
__device__ int           g_off[N_ENT + 1];
__device__ int           g_cur[N_ENT];
__device__ uint32_t      g_pay[N_EDGES];   // (rel<<16) | src, grouped by dst

// ---------------------------------------------------------------------------
// helpers
// ---------------------------------------------------------------------------
__device__ __forceinline__ uint32_t smem_u32(const void* p) {
    uint32_t a;
    asm("{ .reg .u64 t; cvta.to.shared.u64 t, %1; cvt.u32.u64 %0, t; }"
        : "=r"(a) : "l"(p));
    return a;
}

#define LDMX4(r0, r1, r2, r3, addr)                                           \
    asm volatile("ldmatrix.sync.aligned.m8n8.x4.shared.b16 {%0,%1,%2,%3}, [%4];" \
                 : "=r"(r0), "=r"(r1), "=r"(r2), "=r"(r3) : "r"(addr))

#define MMA_BF16(C, A, B)                                                     \
    asm volatile(                                                             \
        "mma.sync.aligned.m16n8k16.row.col.f32.bf16.bf16.f32 "                \
        "{%0,%1,%2,%3}, {%4,%5,%6,%7}, {%8,%9}, {%0,%1,%2,%3};"               \
        : "+f"((C)[0]), "+f"((C)[1]), "+f"((C)[2]), "+f"((C)[3])              \
        : "r"((A)[0]), "r"((A)[1]), "r"((A)[2]), "r"((A)[3]),                 \
          "r"((B)[0]), "r"((B)[1]))

#define CP_ASYNC16(dst, src)                                                  \
    asm volatile("cp.async.cg.shared.global [%0], [%1], 16;"                  \
                 :: "r"(dst), "l"(src))
#define CP_COMMIT()  asm volatile("cp.async.commit_group;" ::: "memory")
#define CP_WAIT0()   asm volatile("cp.async.wait_group 0;" ::: "memory")

__device__ __forceinline__ uint32_t bf2x(float a, float b) {
    __nv_bfloat162 t(__float2bfloat16(a), __float2bfloat16(b));
    return *(uint32_t*)&t;
}

// ---------------------------------------------------------------------------
// Edge binning by dst. hist expects cnt==0 (static-zero first call; scan
// re-zeroes for subsequent graph replays).
// ---------------------------------------------------------------------------
__global__ void hist_kernel(const int* __restrict__ dst,
                            int* __restrict__ cnt, int E)
{
    int e = blockIdx.x * blockDim.x + threadIdx.x;
    if (e >= E) return;
    atomicAdd(&cnt[dst[e]], 1);
}

__global__ __launch_bounds__(1024)
void scan_kernel(int* __restrict__ cnt,
                 int* __restrict__ off, int* __restrict__ cur)
{
    __shared__ int ps[1024];
    const int t = threadIdx.x;
    const int CH = (N_ENT + 1023) / 1024;
    const int lo = t * CH;
    const int hi = min(lo + CH, N_ENT);
    int s = 0;
    for (int i = lo; i < hi; i++) s += cnt[i];
    ps[t] = s;
    __syncthreads();
    for (int d = 1; d < 1024; d <<= 1) {
        int v = (t >= d) ? ps[t - d] : 0;
        __syncthreads();
        ps[t] += v;
        __syncthreads();
    }
    int run = ps[t] - s;
    for (int i = lo; i < hi; i++) {
        off[i] = run;
        cur[i] = run;
        run += cnt[i];
        cnt[i] = 0;
    }
    if (t == 1023) off[N_ENT] = run;
}

__global__ void fill_kernel(const int* __restrict__ src,
                            const int* __restrict__ dst,
                            const int* __restrict__ rel,
                            int* __restrict__ cur,
                            uint32_t* __restrict__ pay, int E)
{
    int e = blockIdx.x * blockDim.x + threadIdx.x;
    if (e >= E) return;
    int pos = atomicAdd(&cur[dst[e]], 1);
    pay[pos] = ((uint32_t)rel[e] << 16) | (uint32_t)src[e];
}

// ---------------------------------------------------------------------------
// Aggregate: warp per dst node (R12 scalar-FFMA core, proven 77.7us).
// compact[n,b] = sum_edges w_comp[rel,b]*h[src]; fp32 accum, no atomics.
// Only delta vs R12: wc row fetched with 2 x ld.shared.v4.f32 (broadcast)
// instead of 8 scalar LDS.
// ---------------------------------------------------------------------------
__global__ __launch_bounds__(256)
void agg_kernel(const float* __restrict__ h,
                const uint32_t* __restrict__ pay,
                const int* __restrict__ off,
                const float* __restrict__ w_comp,
                __nv_bfloat16* __restrict__ comp_hi,
                __nv_bfloat16* __restrict__ comp_lo,
                int relu)
{
    __shared__ float wc[N_REL][N_BASES];
    const int tid = threadIdx.x;
    if (tid < N_REL * N_BASES) wc[tid >> 3][tid & 7] = w_comp[tid];
    __syncthreads();

    const int w    = (blockIdx.x * blockDim.x + tid) >> 5;
    const int lane = tid & 31;
    if (w >= N_ENT) return;

    const int o0 = off[w];
    const int n  = off[w + 1] - o0;

    float cb[N_BASES][4];
#pragma unroll
    for (int b = 0; b < N_BASES; b++)
#pragma unroll
        for (int c = 0; c < 4; c++) cb[b][c] = 0.f;

    const uint32_t wcbase = smem_u32(&wc[0][0]);

    for (int e = 0; e < n; e++) {
        uint32_t p = pay[o0 + e];
        int r = (int)(p >> 16);
        int s = (int)(p & 0xFFFFu);
        float4 v = *(const float4*)(h + (size_t)s * H_DIM + lane * 4);
        if (relu) {
            v.x = fmaxf(v.x, 0.f); v.y = fmaxf(v.y, 0.f);
            v.z = fmaxf(v.z, 0.f); v.w = fmaxf(v.w, 0.f);
        }
        // wc row: 2 x LDS.128 broadcast
        float w0, w1, w2, w3, w4, w5, w6, w7;
        uint32_t wrow = wcbase + (uint32_t)r * (N_BASES * 4);
        asm("ld.shared.v4.f32 {%0,%1,%2,%3}, [%4];"
            : "=f"(w0), "=f"(w1), "=f"(w2), "=f"(w3) : "r"(wrow));
        asm("ld.shared.v4.f32 {%0,%1,%2,%3}, [%4];"
            : "=f"(w4), "=f"(w5), "=f"(w6), "=f"(w7) : "r"(wrow + 16));
        float wcv[8] = {w0, w1, w2, w3, w4, w5, w6, w7};
#pragma unroll
        for (int b = 0; b < N_BASES; b++) {
            float wcb = wcv[b];
            cb[b][0] = fmaf(wcb, v.x, cb[b][0]);
            cb[b][1] = fmaf(wcb, v.y, cb[b][1]);
            cb[b][2] = fmaf(wcb, v.z, cb[b][2]);
            cb[b][3] = fmaf(wcb, v.w, cb[b][3]);
        }
    }

#pragma unroll
    for (int b = 0; b < N_BASES; b++) {
        size_t base = ((size_t)b * N_ENT + w) * H_DIM + lane * 4;
        float hi[4], lo[4];
#pragma unroll
        for (int c = 0; c < 4; c++) {
            hi[c] = __bfloat162float(__float2bfloat16(cb[b][c]));
            lo[c] = cb[b][c] - hi[c];
        }
        uint2 uh, ul;
        uh.x = bf2x(hi[0], hi[1]); uh.y = bf2x(hi[2], hi[3]);
        ul.x = bf2x(lo[0], lo[1]); ul.y = bf2x(lo[2], lo[3]);
        *(uint2*)(comp_hi + base) = uh;
        *(uint2*)(comp_lo + base) = ul;
    }
}

// ---------------------------------------------------------------------------
// Prep W planes: g<8 -> basis[g] transposed [o][i]; g==8 -> loop_w transposed.
// ---------------------------------------------------------------------------
__global__ void prep_w_kernel(const float* __restrict__ basis,
                              const float* __restrict__ loop_w,
                              __nv_bfloat16* __restrict__ Wt_hi,
                              __nv_bfloat16* __restrict__ Wt_lo)
{
    int idx = blockIdx.x * blockDim.x + threadIdx.x;
    const int total = 9 * H_DIM * H_DIM;
    if (idx >= total) return;
    int g  = idx >> 14;
    int io = idx & 16383;                  // i*128 + o
    float s = (g < 8) ? basis[g * 16384 + io] : loop_w[io];
    int i = io >> 7, o = io & 127;
    size_t oidx = (size_t)g * 16384 + o * 128 + i;
    __nv_bfloat16 hi = __float2bfloat16(s);
    __nv_bfloat16 lo = __float2bfloat16(s - __bfloat162float(hi));
    Wt_hi[oidx] = hi;
    Wt_lo[oidx] = lo;
}

// ---------------------------------------------------------------------------
// Split input activations fp32 -> bf16 hi/lo (optional fused ReLU).
// ---------------------------------------------------------------------------
__global__ void split_kernel(const float* __restrict__ x,
                             __nv_bfloat16* __restrict__ hi,
                             __nv_bfloat16* __restrict__ lo,
                             int n4, int relu)
{
    int i = blockIdx.x * blockDim.x + threadIdx.x;
    if (i >= n4) return;
    float4 v = ((const float4*)x)[i];
    if (relu) {
        v.x = fmaxf(v.x, 0.f); v.y = fmaxf(v.y, 0.f);
        v.z = fmaxf(v.z, 0.f); v.w = fmaxf(v.w, 0.f);
    }
    float e[4] = {v.x, v.y, v.z, v.w};
    __nv_bfloat16 h[4], l[4];
#pragma unroll
    for (int j = 0; j < 4; j++) {
        h[j] = __float2bfloat16(e[j]);
        l[j] = __float2bfloat16(e[j] - __bfloat162float(h[j]));
    }
    ((__nv_bfloat162*)hi)[2 * i]     = __nv_bfloat162(h[0], h[1]);
    ((__nv_bfloat162*)hi)[2 * i + 1] = __nv_bfloat162(h[2], h[3]);
    ((__nv_bfloat162*)lo)[2 * i]     = __nv_bfloat162(l[0], l[1]);
    ((__nv_bfloat162*)lo)[2 * i + 1] = __nv_bfloat162(l[2], l[3]);
}

// ---------------------------------------------------------------------------
// Single K=1152 GEMM: OUT = [compact_0..7 | h] @ [[basis_0..7];[loop]] + bias.
// CTA tile 128x128, 8 warps (4M x 2N), warp tile 32x64, 3-term bf16 split,
// fp32 acc across whole K, double-buffered cp.async stages. Optional fused
// ReLU on the output (final layer).
// ---------------------------------------------------------------------------
#define PITCH9   144
#define ST_A_HI  0
#define ST_A_LO  18432
#define ST_W_HI  36864
#define ST_W_LO  55296
#define STAGE_SZ 73728
#define GEMM_SMEM (2 * STAGE_SZ)        // 147456

__global__ __launch_bounds__(256, 1)
void gemm9_kernel(const __nv_bfloat16* __restrict__ comp_hi,
                  const __nv_bfloat16* __restrict__ comp_lo,
                  const __nv_bfloat16* __restrict__ Ahi,
                  const __nv_bfloat16* __restrict__ Alo,
                  const __nv_bfloat16* __restrict__ Wthi,
                  const __nv_bfloat16* __restrict__ Wtlo,
                  const float* __restrict__ bias,
                  float* __restrict__ OUT,
                  int M, int relu)
{
    extern __shared__ char smem[];
    const uint32_t sb = smem_u32(smem);
    const int tid   = threadIdx.x;
    const int wid   = tid >> 5;
    const int lane  = tid & 31;
    const int wm    = wid >> 1;
    const int wn    = wid & 1;
    const int m0    = blockIdx.x * 128;

    const int q   = lane >> 3;
    const int r8  = lane & 7;
    const int arow_base = wm * 32 + r8 + (q & 1) * 8;
    const int acol_add  = (q >> 1) * 8;
    const int brow_base = wn * 64 + (q >> 1) * 8 + r8;
    const int bcol_add  = (q & 1) * 8;
    const int gr0 = m0 + wm * 32 + (lane >> 2);

#define PREFETCH(t)                                                           \
    do {                                                                      \
        const int _g = (t) >> 1, _hf = (t) & 1;                               \
        const __nv_bfloat16* _ah = (_g < 8)                                   \
            ? comp_hi + (size_t)_g * N_ENT * H_DIM : Ahi;                     \
        const __nv_bfloat16* _al = (_g < 8)                                   \
            ? comp_lo + (size_t)_g * N_ENT * H_DIM : Alo;                     \
        const __nv_bfloat16* _wh = Wthi + _g * 16384;                         \
        const __nv_bfloat16* _wl = Wtlo + _g * 16384;                         \
        const uint32_t _st = sb + ((t) & 1) * STAGE_SZ;                       \
        _Pragma("unroll")                                                     \
        for (int _i = 0; _i < 4; _i++) {                                      \
            int _idx = tid + _i * 256;                                        \
            int _row = _idx >> 3;                                             \
            int _c8  = (_idx & 7) * 8;                                        \
            uint32_t _sa = _st + _row * PITCH9 + _c8 * 2;                     \
            if (m0 + _row < M) {                                              \
                CP_ASYNC16(_sa + ST_A_HI,                                     \
                    _ah + (size_t)(m0 + _row) * H_DIM + _hf * 64 + _c8);      \
                CP_ASYNC16(_sa + ST_A_LO,                                     \
                    _al + (size_t)(m0 + _row) * H_DIM + _hf * 64 + _c8);      \
            } else {                                                          \
                *(uint4*)(smem + (_sa + ST_A_HI - sb)) = make_uint4(0,0,0,0); \
                *(uint4*)(smem + (_sa + ST_A_LO - sb)) = make_uint4(0,0,0,0); \
            }                                                                 \
            CP_ASYNC16(_sa + ST_W_HI,                                         \
                _wh + (size_t)_row * H_DIM + _hf * 64 + _c8);                 \
            CP_ASYNC16(_sa + ST_W_LO,                                         \
                _wl + (size_t)_row * H_DIM + _hf * 64 + _c8);                 \
        }                                                                     \
    } while (0)

    float acc[2][8][4];
#pragma unroll
    for (int mt = 0; mt < 2; mt++)
#pragma unroll
        for (int nt = 0; nt < 8; nt++)
#pragma unroll
            for (int c = 0; c < 4; c++) acc[mt][nt][c] = 0.f;

    PREFETCH(0);
    CP_COMMIT();

    for (int t = 0; t < 18; t++) {
        CP_WAIT0();
        __syncthreads();

        if (t < 17) {
            PREFETCH(t + 1);
            CP_COMMIT();
        }

        const uint32_t st = sb + (t & 1) * STAGE_SZ;

#pragma unroll
        for (int ks = 0; ks < 4; ks++) {
            const int k0 = ks * 16;
            uint32_t ah[2][4], al[2][4], bh[8][2], bl[8][2];
#pragma unroll
            for (int mt = 0; mt < 2; mt++) {
                uint32_t off = (uint32_t)((arow_base + mt * 16) * PITCH9
                                          + (k0 + acol_add) * 2);
                LDMX4(ah[mt][0], ah[mt][1], ah[mt][2], ah[mt][3],
                      st + ST_A_HI + off);
                LDMX4(al[mt][0], al[mt][1], al[mt][2], al[mt][3],
                      st + ST_A_LO + off);
            }
#pragma unroll
            for (int p = 0; p < 4; p++) {
                uint32_t off = (uint32_t)((brow_base + p * 16) * PITCH9
                                          + (k0 + bcol_add) * 2);
                LDMX4(bh[2 * p][0], bh[2 * p][1], bh[2 * p + 1][0],
                      bh[2 * p + 1][1], st + ST_W_HI + off);
                LDMX4(bl[2 * p][0], bl[2 * p][1], bl[2 * p + 1][0],
                      bl[2 * p + 1][1], st + ST_W_LO + off);
            }
#pragma unroll
            for (int mt = 0; mt < 2; mt++)
#pragma unroll
                for (int nt = 0; nt < 8; nt++) {
                    MMA_BF16(acc[mt][nt], ah[mt], bh[nt]);
                    MMA_BF16(acc[mt][nt], ah[mt], bl[nt]);
                    MMA_BF16(acc[mt][nt], al[mt], bh[nt]);
                }
        }
        __syncthreads();
    }

    // ---- epilogue: OUT = acc + bias (optional ReLU) ----
#pragma unroll
    for (int mt = 0; mt < 2; mt++) {
        int row = gr0 + mt * 16;
#pragma unroll
        for (int nt = 0; nt < 8; nt++) {
            int col = wn * 64 + nt * 8 + (lane & 3) * 2;
            float2 bv = *(const float2*)(bias + col);
            float o0 = acc[mt][nt][0] + bv.x, o1 = acc[mt][nt][1] + bv.y;
            float o2 = acc[mt][nt][2] + bv.x, o3 = acc[mt][nt][3] + bv.y;
            if (relu) {
                o0 = fmaxf(o0, 0.f); o1 = fmaxf(o1, 0.f);
                o2 = fmaxf(o2, 0.f); o3 = fmaxf(o3, 0.f);
            }
            if (row < M)
                *(float2*)(OUT + (size_t)row * H_DIM + col) = make_float2(o0, o1);
            if (row + 8 < M)
                *(float2*)(OUT + (size_t)(row + 8) * H_DIM + col) = make_float2(o2, o3);
        }
    }
#undef PREFETCH
}

// ---------------------------------------------------------------------------
// Launch. agg1 is the 4th launch -> ncu-profiled.
// ---------------------------------------------------------------------------
extern "C" void kernel_launch(void* const* d_in, const int* in_sizes, int n_in,
                              void* d_out, int out_size)
{
    const float* entity_emb = (const float*)d_in[0];
    const float* basis1     = (const float*)d_in[1];
    const float* w_comp1    = (const float*)d_in[2];
    const float* loop_w1    = (const float*)d_in[3];
    const float* bias1      = (const float*)d_in[4];
    const float* basis2     = (const float*)d_in[5];
    const float* w_comp2    = (const float*)d_in[6];
    const float* loop_w2    = (const float*)d_in[7];
    const float* bias2      = (const float*)d_in[8];
    const int*   src        = (const int*)d_in[9];
    const int*   dst        = (const int*)d_in[10];
    const int*   rel        = (const int*)d_in[11];
    float*       out        = (float*)d_out;

    const int E = in_sizes[9];

    __nv_bfloat16 *dWth, *dWtl, *dAh, *dAl, *dCh, *dCl;
    float *dH1;
    int *dcnt, *doff, *dcur;
    uint32_t *dpay;
    cudaGetSymbolAddress((void**)&dWth, g_Wt_hi);
    cudaGetSymbolAddress((void**)&dWtl, g_Wt_lo);
    cudaGetSymbolAddress((void**)&dAh,  g_A_hi);
    cudaGetSymbolAddress((void**)&dAl,  g_A_lo);
    cudaGetSymbolAddress((void**)&dCh,  g_comp_hi);
    cudaGetSymbolAddress((void**)&dCl,  g_comp_lo);
    cudaGetSymbolAddress((void**)&dH1,  g_H1);
    cudaGetSymbolAddress((void**)&dcnt, g_cnt);
    cudaGetSymbolAddress((void**)&doff, g_off);
    cudaGetSymbolAddress((void**)&dcur, g_cur);
    cudaGetSymbolAddress((void**)&dpay, g_pay);

    cudaFuncSetAttribute(gemm9_kernel,
                         cudaFuncAttributeMaxDynamicSharedMemorySize, GEMM_SMEM);

    const int pw_blocks = (9 * H_DIM * H_DIM + 255) / 256;
    const int n4        = N_ENT * H_DIM / 4;
    const int sp_blocks = (n4 + 255) / 256;
    const int eg_blocks = (E + 255) / 256;
    const int gemm_grid = (N_ENT + 127) / 128;       // 391
    const int agg_blocks = (N_ENT * 32 + 255) / 256;

    // ---------------- binning (cnt pre-zeroed; scan re-zeroes) ----------------
    hist_kernel<<<eg_blocks, 256>>>(dst, dcnt, E);
    scan_kernel<<<1, 1024>>>(dcnt, doff, dcur);
    fill_kernel<<<eg_blocks, 256>>>(src, dst, rel, dcur, dpay, E);

    // ---------------- Layer 1 ----------------
    agg_kernel<<<agg_blocks, 256>>>(entity_emb, dpay, doff, w_comp1,
                                    dCh, dCl, 0);              // profiled (#4)
    prep_w_kernel<<<pw_blocks, 256>>>(basis1, loop_w1, dWth, dWtl);
    split_kernel<<<sp_blocks, 256>>>(entity_emb, dAh, dAl, n4, 0);
    gemm9_kernel<<<gemm_grid, 256, GEMM_SMEM>>>(dCh, dCl, dAh, dAl,
                                                dWth, dWtl, bias1, dH1,
                                                N_ENT, 0);

    // ---------------- Layer 2 ----------------
    agg_kernel<<<agg_blocks, 256>>>(dH1, dpay, doff, w_comp2,
                                    dCh, dCl, 1);              // fused ReLU
    prep_w_kernel<<<pw_blocks, 256>>>(basis2, loop_w2, dWth, dWtl);
    split_kernel<<<sp_blocks, 256>>>(dH1, dAh, dAl, n4, 1);    // fused ReLU
    gemm9_kernel<<<gemm_grid, 256, GEMM_SMEM>>>(dCh, dCl, dAh, dAl,
                                                dWth, dWtl, bias2, out,
                                                N_ENT, 1);     // fused ReLU
}

// round 16
// speedup vs baseline: 1.5425x; 1.0064x over previous
#include <cuda_runtime.h>
#include <cuda_bf16.h>
#include <cstdint>

// Problem constants (fixed by the reference).
#define N_ENT   50000
#define N_REL   16
#define N_BASES 8
#define H_DIM   128
#define N_EDGES 800000

// ---------------------------------------------------------------------------
// Device scratch (allocation-free rule: __device__ globals).
// ---------------------------------------------------------------------------
__device__ __nv_bfloat16 g_Wt_hi[9 * H_DIM * H_DIM];   // [g][o][i]
__device__ __nv_bfloat16 g_Wt_lo[9 * H_DIM * H_DIM];
__device__ __nv_bfloat16 g_A_hi[(size_t)N_ENT * H_DIM];
__device__ __nv_bfloat16 g_A_lo[(size_t)N_ENT * H_DIM];
__device__ __nv_bfloat16 g_comp_hi[(size_t)N_BASES * N_ENT * H_DIM];
__device__ __nv_bfloat16 g_comp_lo[(size_t)N_BASES * N_ENT * H_DIM];
__device__ float         g_H1[(size_t)N_ENT * H_DIM];
__device__ int           g_cnt[N_ENT];
__device__ int           g_off[N_ENT + 1];
__device__ int           g_cur[N_ENT];
__device__ uint32_t      g_pay[N_EDGES];   // (rel<<16) | src, grouped by dst

// ---------------------------------------------------------------------------
// helpers
// ---------------------------------------------------------------------------
__device__ __forceinline__ uint32_t smem_u32(const void* p) {
    uint32_t a;
    asm("{ .reg .u64 t; cvta.to.shared.u64 t, %1; cvt.u32.u64 %0, t; }"
        : "=r"(a) : "l"(p));
    return a;
}

#define LDMX4(r0, r1, r2, r3, addr)                                           \
    asm volatile("ldmatrix.sync.aligned.m8n8.x4.shared.b16 {%0,%1,%2,%3}, [%4];" \
                 : "=r"(r0), "=r"(r1), "=r"(r2), "=r"(r3) : "r"(addr))

#define MMA_BF16(C, A, B)                                                     \
    asm volatile(                                                             \
        "mma.sync.aligned.m16n8k16.row.col.f32.bf16.bf16.f32 "                \
        "{%0,%1,%2,%3}, {%4,%5,%6,%7}, {%8,%9}, {%0,%1,%2,%3};"               \
        : "+f"((C)[0]), "+f"((C)[1]), "+f"((C)[2]), "+f"((C)[3])              \
        : "r"((A)[0]), "r"((A)[1]), "r"((A)[2]), "r"((A)[3]),                 \
          "r"((B)[0]), "r"((B)[1]))

#define CP_ASYNC16(dst, src)                                                  \
    asm volatile("cp.async.cg.shared.global [%0], [%1], 16;"                  \
                 :: "r"(dst), "l"(src))
#define CP_COMMIT()  asm volatile("cp.async.commit_group;" ::: "memory")
#define CP_WAIT1()   asm volatile("cp.async.wait_group 1;" ::: "memory")

__device__ __forceinline__ uint32_t bf2x(float a, float b) {
    __nv_bfloat162 t(__float2bfloat16(a), __float2bfloat16(b));
    return *(uint32_t*)&t;
}

// ---------------------------------------------------------------------------
// Edge binning by dst. hist expects cnt==0 (static-zero first call; scan
// re-zeroes for subsequent graph replays).
// ---------------------------------------------------------------------------
__global__ void hist_kernel(const int* __restrict__ dst,
                            int* __restrict__ cnt, int E)
{
    int e = blockIdx.x * blockDim.x + threadIdx.x;
    if (e >= E) return;
    atomicAdd(&cnt[dst[e]], 1);
}

__global__ __launch_bounds__(1024)
void scan_kernel(int* __restrict__ cnt,
                 int* __restrict__ off, int* __restrict__ cur)
{
    __shared__ int ps[1024];
    const int t = threadIdx.x;
    const int CH = (N_ENT + 1023) / 1024;
    const int lo = t * CH;
    const int hi = min(lo + CH, N_ENT);
    int s = 0;
    for (int i = lo; i < hi; i++) s += cnt[i];
    ps[t] = s;
    __syncthreads();
    for (int d = 1; d < 1024; d <<= 1) {
        int v = (t >= d) ? ps[t - d] : 0;
        __syncthreads();
        ps[t] += v;
        __syncthreads();
    }
    int run = ps[t] - s;
    for (int i = lo; i < hi; i++) {
        off[i] = run;
        cur[i] = run;
        run += cnt[i];
        cnt[i] = 0;
    }
    if (t == 1023) off[N_ENT] = run;
}

__global__ void fill_kernel(const int* __restrict__ src,
                            const int* __restrict__ dst,
                            const int* __restrict__ rel,
                            int* __restrict__ cur,
                            uint32_t* __restrict__ pay, int E)
{
    int e = blockIdx.x * blockDim.x + threadIdx.x;
    if (e >= E) return;
    int pos = atomicAdd(&cur[dst[e]], 1);
    pay[pos] = ((uint32_t)rel[e] << 16) | (uint32_t)src[e];
}

// ---------------------------------------------------------------------------
// Aggregate: warp per dst node (proven 78us).
// compact[n,b] = sum_edges w_comp[rel,b]*h[src]; fp32 accum, no atomics.
// ---------------------------------------------------------------------------
__global__ __launch_bounds__(256)
void agg_kernel(const float* __restrict__ h,
                const uint32_t* __restrict__ pay,
                const int* __restrict__ off,
                const float* __restrict__ w_comp,
                __nv_bfloat16* __restrict__ comp_hi,
                __nv_bfloat16* __restrict__ comp_lo,
                int relu)
{
    __shared__ float wc[N_REL][N_BASES];
    const int tid = threadIdx.x;
    if (tid < N_REL * N_BASES) wc[tid >> 3][tid & 7] = w_comp[tid];
    __syncthreads();

    const int w    = (blockIdx.x * blockDim.x + tid) >> 5;
    const int lane = tid & 31;
    if (w >= N_ENT) return;

    const int o0 = off[w];
    const int n  = off[w + 1] - o0;

    float cb[N_BASES][4];
#pragma unroll
    for (int b = 0; b < N_BASES; b++)
#pragma unroll
        for (int c = 0; c < 4; c++) cb[b][c] = 0.f;

    const uint32_t wcbase = smem_u32(&wc[0][0]);

    for (int e = 0; e < n; e++) {
        uint32_t p = pay[o0 + e];
        int r = (int)(p >> 16);
        int s = (int)(p & 0xFFFFu);
        float4 v = *(const float4*)(h + (size_t)s * H_DIM + lane * 4);
        if (relu) {
            v.x = fmaxf(v.x, 0.f); v.y = fmaxf(v.y, 0.f);
            v.z = fmaxf(v.z, 0.f); v.w = fmaxf(v.w, 0.f);
        }
        float w0, w1, w2, w3, w4, w5, w6, w7;
        uint32_t wrow = wcbase + (uint32_t)r * (N_BASES * 4);
        asm("ld.shared.v4.f32 {%0,%1,%2,%3}, [%4];"
            : "=f"(w0), "=f"(w1), "=f"(w2), "=f"(w3) : "r"(wrow));
        asm("ld.shared.v4.f32 {%0,%1,%2,%3}, [%4];"
            : "=f"(w4), "=f"(w5), "=f"(w6), "=f"(w7) : "r"(wrow + 16));
        float wcv[8] = {w0, w1, w2, w3, w4, w5, w6, w7};
#pragma unroll
        for (int b = 0; b < N_BASES; b++) {
            float wcb = wcv[b];
            cb[b][0] = fmaf(wcb, v.x, cb[b][0]);
            cb[b][1] = fmaf(wcb, v.y, cb[b][1]);
            cb[b][2] = fmaf(wcb, v.z, cb[b][2]);
            cb[b][3] = fmaf(wcb, v.w, cb[b][3]);
        }
    }

#pragma unroll
    for (int b = 0; b < N_BASES; b++) {
        size_t base = ((size_t)b * N_ENT + w) * H_DIM + lane * 4;
        float hi[4], lo[4];
#pragma unroll
        for (int c = 0; c < 4; c++) {
            hi[c] = __bfloat162float(__float2bfloat16(cb[b][c]));
            lo[c] = cb[b][c] - hi[c];
        }
        uint2 uh, ul;
        uh.x = bf2x(hi[0], hi[1]); uh.y = bf2x(hi[2], hi[3]);
        ul.x = bf2x(lo[0], lo[1]); ul.y = bf2x(lo[2], lo[3]);
        *(uint2*)(comp_hi + base) = uh;
        *(uint2*)(comp_lo + base) = ul;
    }
}

// ---------------------------------------------------------------------------
// Prep W planes: g<8 -> basis[g] transposed [o][i]; g==8 -> loop_w transposed.
// ---------------------------------------------------------------------------
__global__ void prep_w_kernel(const float* __restrict__ basis,
                              const float* __restrict__ loop_w,
                              __nv_bfloat16* __restrict__ Wt_hi,
                              __nv_bfloat16* __restrict__ Wt_lo)
{
    int idx = blockIdx.x * blockDim.x + threadIdx.x;
    const int total = 9 * H_DIM * H_DIM;
    if (idx >= total) return;
    int g  = idx >> 14;
    int io = idx & 16383;                  // i*128 + o
    float s = (g < 8) ? basis[g * 16384 + io] : loop_w[io];
    int i = io >> 7, o = io & 127;
    size_t oidx = (size_t)g * 16384 + o * 128 + i;
    __nv_bfloat16 hi = __float2bfloat16(s);
    __nv_bfloat16 lo = __float2bfloat16(s - __bfloat162float(hi));
    Wt_hi[oidx] = hi;
    Wt_lo[oidx] = lo;
}

// ---------------------------------------------------------------------------
// Split input activations fp32 -> bf16 hi/lo (optional fused ReLU).
// ---------------------------------------------------------------------------
__global__ void split_kernel(const float* __restrict__ x,
                             __nv_bfloat16* __restrict__ hi,
                             __nv_bfloat16* __restrict__ lo,
                             int n4, int relu)
{
    int i = blockIdx.x * blockDim.x + threadIdx.x;
    if (i >= n4) return;
    float4 v = ((const float4*)x)[i];
    if (relu) {
        v.x = fmaxf(v.x, 0.f); v.y = fmaxf(v.y, 0.f);
        v.z = fmaxf(v.z, 0.f); v.w = fmaxf(v.w, 0.f);
    }
    float e[4] = {v.x, v.y, v.z, v.w};
    __nv_bfloat16 h[4], l[4];
#pragma unroll
    for (int j = 0; j < 4; j++) {
        h[j] = __float2bfloat16(e[j]);
        l[j] = __float2bfloat16(e[j] - __bfloat162float(h[j]));
    }
    ((__nv_bfloat162*)hi)[2 * i]     = __nv_bfloat162(h[0], h[1]);
    ((__nv_bfloat162*)hi)[2 * i + 1] = __nv_bfloat162(h[2], h[3]);
    ((__nv_bfloat162*)lo)[2 * i]     = __nv_bfloat162(l[0], l[1]);
    ((__nv_bfloat162*)lo)[2 * i + 1] = __nv_bfloat162(l[2], l[3]);
}

// ---------------------------------------------------------------------------
// Single K=1152 GEMM: OUT = [compact_0..7 | h] @ [[basis_0..7];[loop]] + bias.
// CTA tile 128x128, 8 warps (4M x 2N), warp tile 32x64, 3-term bf16 split,
// fp32 acc across whole K.  NEW (R16): 3-stage cp.async ring, prefetch
// distance 2, wait_group 1 (never a full drain), ONE barrier per stage.
// Optional fused ReLU on the output (final layer).
// ---------------------------------------------------------------------------
#define PITCH9   144
#define ST_A_HI  0
#define ST_A_LO  18432
#define ST_W_HI  36864
#define ST_W_LO  55296
#define STAGE_SZ 73728
#define GEMM_SMEM (3 * STAGE_SZ)        // 221184 (<= 227KB opt-in)

__global__ __launch_bounds__(256, 1)
void gemm9_kernel(const __nv_bfloat16* __restrict__ comp_hi,
                  const __nv_bfloat16* __restrict__ comp_lo,
                  const __nv_bfloat16* __restrict__ Ahi,
                  const __nv_bfloat16* __restrict__ Alo,
                  const __nv_bfloat16* __restrict__ Wthi,
                  const __nv_bfloat16* __restrict__ Wtlo,
                  const float* __restrict__ bias,
                  float* __restrict__ OUT,
                  int M, int relu)
{
    extern __shared__ char smem[];
    const uint32_t sb = smem_u32(smem);
    const int tid   = threadIdx.x;
    const int wid   = tid >> 5;
    const int lane  = tid & 31;
    const int wm    = wid >> 1;
    const int wn    = wid & 1;
    const int m0    = blockIdx.x * 128;

    const int q   = lane >> 3;
    const int r8  = lane & 7;
    const int arow_base = wm * 32 + r8 + (q & 1) * 8;
    const int acol_add  = (q >> 1) * 8;
    const int brow_base = wn * 64 + (q >> 1) * 8 + r8;
    const int bcol_add  = (q & 1) * 8;
    const int gr0 = m0 + wm * 32 + (lane >> 2);

#define PREFETCH(t)                                                           \
    do {                                                                      \
        const int _g = (t) >> 1, _hf = (t) & 1;                               \
        const __nv_bfloat16* _ah = (_g < 8)                                   \
            ? comp_hi + (size_t)_g * N_ENT * H_DIM : Ahi;                     \
        const __nv_bfloat16* _al = (_g < 8)                                   \
            ? comp_lo + (size_t)_g * N_ENT * H_DIM : Alo;                     \
        const __nv_bfloat16* _wh = Wthi + _g * 16384;                         \
        const __nv_bfloat16* _wl = Wtlo + _g * 16384;                         \
        const uint32_t _st = sb + ((t) % 3) * STAGE_SZ;                       \
        _Pragma("unroll")                                                     \
        for (int _i = 0; _i < 4; _i++) {                                      \
            int _idx = tid + _i * 256;                                        \
            int _row = _idx >> 3;                                             \
            int _c8  = (_idx & 7) * 8;                                        \
            uint32_t _sa = _st + _row * PITCH9 + _c8 * 2;                     \
            if (m0 + _row < M) {                                              \
                CP_ASYNC16(_sa + ST_A_HI,                                     \
                    _ah + (size_t)(m0 + _row) * H_DIM + _hf * 64 + _c8);      \
                CP_ASYNC16(_sa + ST_A_LO,                                     \
                    _al + (size_t)(m0 + _row) * H_DIM + _hf * 64 + _c8);      \
            } else {                                                          \
                *(uint4*)(smem + (_sa + ST_A_HI - sb)) = make_uint4(0,0,0,0); \
                *(uint4*)(smem + (_sa + ST_A_LO - sb)) = make_uint4(0,0,0,0); \
            }                                                                 \
            CP_ASYNC16(_sa + ST_W_HI,                                         \
                _wh + (size_t)_row * H_DIM + _hf * 64 + _c8);                 \
            CP_ASYNC16(_sa + ST_W_LO,                                         \
                _wl + (size_t)_row * H_DIM + _hf * 64 + _c8);                 \
        }                                                                     \
    } while (0)

    float acc[2][8][4];
#pragma unroll
    for (int mt = 0; mt < 2; mt++)
#pragma unroll
        for (int nt = 0; nt < 8; nt++)
#pragma unroll
            for (int c = 0; c < 4; c++) acc[mt][nt][c] = 0.f;

    // prologue: stages 0 and 1 in flight (prefetch distance 2)
    PREFETCH(0);
    CP_COMMIT();
    PREFETCH(1);
    CP_COMMIT();

    for (int t = 0; t < 18; t++) {
        // outstanding groups: {t, t+1}. wait until <=1 remains -> stage t done.
        CP_WAIT1();
        __syncthreads();     // stage-t data visible to all; prev compute done

        // prefetch t+2 into buffer (t+2)%3 (its last reader finished at t-1)
        if (t + 2 < 18) PREFETCH(t + 2);
        CP_COMMIT();         // commit every iteration (possibly empty group)

        const uint32_t st = sb + (t % 3) * STAGE_SZ;

#pragma unroll
        for (int ks = 0; ks < 4; ks++) {
            const int k0 = ks * 16;
            uint32_t ah[2][4], al[2][4], bh[8][2], bl[8][2];
#pragma unroll
            for (int mt = 0; mt < 2; mt++) {
                uint32_t off = (uint32_t)((arow_base + mt * 16) * PITCH9
                                          + (k0 + acol_add) * 2);
                LDMX4(ah[mt][0], ah[mt][1], ah[mt][2], ah[mt][3],
                      st + ST_A_HI + off);
                LDMX4(al[mt][0], al[mt][1], al[mt][2], al[mt][3],
                      st + ST_A_LO + off);
            }
#pragma unroll
            for (int p = 0; p < 4; p++) {
                uint32_t off = (uint32_t)((brow_base + p * 16) * PITCH9
                                          + (k0 + bcol_add) * 2);
                LDMX4(bh[2 * p][0], bh[2 * p][1], bh[2 * p + 1][0],
                      bh[2 * p + 1][1], st + ST_W_HI + off);
                LDMX4(bl[2 * p][0], bl[2 * p][1], bl[2 * p + 1][0],
                      bl[2 * p + 1][1], st + ST_W_LO + off);
            }
#pragma unroll
            for (int mt = 0; mt < 2; mt++)
#pragma unroll
                for (int nt = 0; nt < 8; nt++) {
                    MMA_BF16(acc[mt][nt], ah[mt], bh[nt]);
                    MMA_BF16(acc[mt][nt], ah[mt], bl[nt]);
                    MMA_BF16(acc[mt][nt], al[mt], bh[nt]);
                }
        }
    }

    // ---- epilogue: OUT = acc + bias (optional ReLU) ----
#pragma unroll
    for (int mt = 0; mt < 2; mt++) {
        int row = gr0 + mt * 16;
#pragma unroll
        for (int nt = 0; nt < 8; nt++) {
            int col = wn * 64 + nt * 8 + (lane & 3) * 2;
            float2 bv = *(const float2*)(bias + col);
            float o0 = acc[mt][nt][0] + bv.x, o1 = acc[mt][nt][1] + bv.y;
            float o2 = acc[mt][nt][2] + bv.x, o3 = acc[mt][nt][3] + bv.y;
            if (relu) {
                o0 = fmaxf(o0, 0.f); o1 = fmaxf(o1, 0.f);
                o2 = fmaxf(o2, 0.f); o3 = fmaxf(o3, 0.f);
            }
            if (row < M)
                *(float2*)(OUT + (size_t)row * H_DIM + col) = make_float2(o0, o1);
            if (row + 8 < M)
                *(float2*)(OUT + (size_t)(row + 8) * H_DIM + col) = make_float2(o2, o3);
        }
    }
#undef PREFETCH
}

// ---------------------------------------------------------------------------
// Launch. agg1 is the 4th launch -> ncu-profiled.
// ---------------------------------------------------------------------------
extern "C" void kernel_launch(void* const* d_in, const int* in_sizes, int n_in,
                              void* d_out, int out_size)
{
    const float* entity_emb = (const float*)d_in[0];
    const float* basis1     = (const float*)d_in[1];
    const float* w_comp1    = (const float*)d_in[2];
    const float* loop_w1    = (const float*)d_in[3];
    const float* bias1      = (const float*)d_in[4];
    const float* basis2     = (const float*)d_in[5];
    const float* w_comp2    = (const float*)d_in[6];
    const float* loop_w2    = (const float*)d_in[7];
    const float* bias2      = (const float*)d_in[8];
    const int*   src        = (const int*)d_in[9];
    const int*   dst        = (const int*)d_in[10];
    const int*   rel        = (const int*)d_in[11];
    float*       out        = (float*)d_out;

    const int E = in_sizes[9];

    __nv_bfloat16 *dWth, *dWtl, *dAh, *dAl, *dCh, *dCl;
    float *dH1;
    int *dcnt, *doff, *dcur;
    uint32_t *dpay;
    cudaGetSymbolAddress((void**)&dWth, g_Wt_hi);
    cudaGetSymbolAddress((void**)&dWtl, g_Wt_lo);
    cudaGetSymbolAddress((void**)&dAh,  g_A_hi);
    cudaGetSymbolAddress((void**)&dAl,  g_A_lo);
    cudaGetSymbolAddress((void**)&dCh,  g_comp_hi);
    cudaGetSymbolAddress((void**)&dCl,  g_comp_lo);
    cudaGetSymbolAddress((void**)&dH1,  g_H1);
    cudaGetSymbolAddress((void**)&dcnt, g_cnt);
    cudaGetSymbolAddress((void**)&doff, g_off);
    cudaGetSymbolAddress((void**)&dcur, g_cur);
    cudaGetSymbolAddress((void**)&dpay, g_pay);

    cudaFuncSetAttribute(gemm9_kernel,
                         cudaFuncAttributeMaxDynamicSharedMemorySize, GEMM_SMEM);

    const int pw_blocks = (9 * H_DIM * H_DIM + 255) / 256;
    const int n4        = N_ENT * H_DIM / 4;
    const int sp_blocks = (n4 + 255) / 256;
    const int eg_blocks = (E + 255) / 256;
    const int gemm_grid = (N_ENT + 127) / 128;       // 391
    const int agg_blocks = (N_ENT * 32 + 255) / 256;

    // ---------------- binning (cnt pre-zeroed; scan re-zeroes) ----------------
    hist_kernel<<<eg_blocks, 256>>>(dst, dcnt, E);
    scan_kernel<<<1, 1024>>>(dcnt, doff, dcur);
    fill_kernel<<<eg_blocks, 256>>>(src, dst, rel, dcur, dpay, E);

    // ---------------- Layer 1 ----------------
    agg_kernel<<<agg_blocks, 256>>>(entity_emb, dpay, doff, w_comp1,
                                    dCh, dCl, 0);              // profiled (#4)
    prep_w_kernel<<<pw_blocks, 256>>>(basis1, loop_w1, dWth, dWtl);
    split_kernel<<<sp_blocks, 256>>>(entity_emb, dAh, dAl, n4, 0);
    gemm9_kernel<<<gemm_grid, 256, GEMM_SMEM>>>(dCh, dCl, dAh, dAl,
                                                dWth, dWtl, bias1, dH1,
                                                N_ENT, 0);

    // ---------------- Layer 2 ----------------
    agg_kernel<<<agg_blocks, 256>>>(dH1, dpay, doff, w_comp2,
                                    dCh, dCl, 1);              // fused ReLU
    prep_w_kernel<<<pw_blocks, 256>>>(basis2, loop_w2, dWth, dWtl);
    split_kernel<<<sp_blocks, 256>>>(dH1, dAh, dAl, n4, 1);    // fused ReLU
    gemm9_kernel<<<gemm_grid, 256, GEMM_SMEM>>>(dCh, dCl, dAh, dAl,
                                                dWth, dWtl, bias2, out,
                                                N_ENT, 1);     // fused ReLU
}

// round 17
// speedup vs baseline: 1.9099x; 1.2381x over previous
#include <cuda_runtime.h>
#include <cuda_fp16.h>
#include <cstdint>

// Problem constants (fixed by the reference).
#define N_ENT   50000
#define N_REL   16
#define N_BASES 8
#define H_DIM   128
#define N_EDGES 800000

// ---------------------------------------------------------------------------
// Device scratch (allocation-free rule: __device__ globals).
// g_Wt  : 9 planes [g][o][i] fp16 hi/lo  (g<8: basis_b transposed; g=8: loop_w)
// g_comp: 8 planes [b][n][128] fp16      (relation-compressed aggregates)
// g_Af  : [n][128] fp16                  (activations, relu-applied as needed)
// ---------------------------------------------------------------------------
__device__ __half  g_Wt_hi[9 * H_DIM * H_DIM];
__device__ __half  g_Wt_lo[9 * H_DIM * H_DIM];
__device__ __half  g_Af[(size_t)N_ENT * H_DIM];
__device__ __half  g_comp[(size_t)N_BASES * N_ENT * H_DIM];
__device__ float   g_H1[(size_t)N_ENT * H_DIM];
__device__ int     g_cnt[N_ENT];
__device__ int     g_off[N_ENT + 1];
__device__ int     g_cur[N_ENT];
__device__ uint32_t g_pay[N_EDGES];   // (rel<<16) | src, grouped by dst

// ---------------------------------------------------------------------------
// helpers
// ---------------------------------------------------------------------------
__device__ __forceinline__ uint32_t smem_u32(const void* p) {
    uint32_t a;
    asm("{ .reg .u64 t; cvta.to.shared.u64 t, %1; cvt.u32.u64 %0, t; }"
        : "=r"(a) : "l"(p));
    return a;
}

#define LDMX4(r0, r1, r2, r3, addr)                                           \
    asm volatile("ldmatrix.sync.aligned.m8n8.x4.shared.b16 {%0,%1,%2,%3}, [%4];" \
                 : "=r"(r0), "=r"(r1), "=r"(r2), "=r"(r3) : "r"(addr))

#define MMA_F16(C, A, B)                                                      \
    asm volatile(                                                             \
        "mma.sync.aligned.m16n8k16.row.col.f32.f16.f16.f32 "                  \
        "{%0,%1,%2,%3}, {%4,%5,%6,%7}, {%8,%9}, {%0,%1,%2,%3};"               \
        : "+f"((C)[0]), "+f"((C)[1]), "+f"((C)[2]), "+f"((C)[3])              \
        : "r"((A)[0]), "r"((A)[1]), "r"((A)[2]), "r"((A)[3]),                 \
          "r"((B)[0]), "r"((B)[1]))

#define CP_ASYNC16(dst, src)                                                  \
    asm volatile("cp.async.cg.shared.global [%0], [%1], 16;"                  \
                 :: "r"(dst), "l"(src))
#define CP_COMMIT()  asm volatile("cp.async.commit_group;" ::: "memory")
#define CP_WAIT1()   asm volatile("cp.async.wait_group 1;" ::: "memory")

__device__ __forceinline__ uint32_t h2x(float a, float b) {
    __half2 t = __floats2half2_rn(a, b);
    return *(uint32_t*)&t;
}

// ---------------------------------------------------------------------------
// Edge binning by dst (proven). hist expects cnt==0 (static-zero first call;
// scan re-zeroes for replays).
// ---------------------------------------------------------------------------
__global__ void hist_kernel(const int* __restrict__ dst,
                            int* __restrict__ cnt, int E)
{
    int e = blockIdx.x * blockDim.x + threadIdx.x;
    if (e >= E) return;
    atomicAdd(&cnt[dst[e]], 1);
}

__global__ __launch_bounds__(1024)
void scan_kernel(int* __restrict__ cnt,
                 int* __restrict__ off, int* __restrict__ cur)
{
    __shared__ int ps[1024];
    const int t = threadIdx.x;
    const int CH = (N_ENT + 1023) / 1024;
    const int lo = t * CH;
    const int hi = min(lo + CH, N_ENT);
    int s = 0;
    for (int i = lo; i < hi; i++) s += cnt[i];
    ps[t] = s;
    __syncthreads();
    for (int d = 1; d < 1024; d <<= 1) {
        int v = (t >= d) ? ps[t - d] : 0;
        __syncthreads();
        ps[t] += v;
        __syncthreads();
    }
    int run = ps[t] - s;
    for (int i = lo; i < hi; i++) {
        off[i] = run;
        cur[i] = run;
        run += cnt[i];
        cnt[i] = 0;
    }
    if (t == 1023) off[N_ENT] = run;
}

__global__ void fill_kernel(const int* __restrict__ src,
                            const int* __restrict__ dst,
                            const int* __restrict__ rel,
                            int* __restrict__ cur,
                            uint32_t* __restrict__ pay, int E)
{
    int e = blockIdx.x * blockDim.x + threadIdx.x;
    if (e >= E) return;
    int pos = atomicAdd(&cur[dst[e]], 1);
    pay[pos] = ((uint32_t)rel[e] << 16) | (uint32_t)src[e];
}

// ---------------------------------------------------------------------------
// Aggregate + activation split, warp per node w:
//   1) Af[w] = fp16(relu?(h[w]))                (merged old split_kernel)
//   2) comp[b][w] = fp16( sum_edges w_comp[rel,b]*relu?(h[src]) )  fp32 accum
// Single fp16 plane per basis -> half the DRAM writes of the bf16 hi/lo form.
// ---------------------------------------------------------------------------
__global__ __launch_bounds__(256)
void agg_kernel(const float* __restrict__ h,
                const uint32_t* __restrict__ pay,
                const int* __restrict__ off,
                const float* __restrict__ w_comp,
                __half* __restrict__ comp,
                __half* __restrict__ Af,
                int relu)
{
    __shared__ float wc[N_REL][N_BASES];
    const int tid = threadIdx.x;
    if (tid < N_REL * N_BASES) wc[tid >> 3][tid & 7] = w_comp[tid];
    __syncthreads();

    const int w    = (blockIdx.x * blockDim.x + tid) >> 5;
    const int lane = tid & 31;
    if (w >= N_ENT) return;

    // ---- own row -> fp16 A plane ----
    {
        float4 hv = *(const float4*)(h + (size_t)w * H_DIM + lane * 4);
        if (relu) {
            hv.x = fmaxf(hv.x, 0.f); hv.y = fmaxf(hv.y, 0.f);
            hv.z = fmaxf(hv.z, 0.f); hv.w = fmaxf(hv.w, 0.f);
        }
        uint2 u;
        u.x = h2x(hv.x, hv.y);
        u.y = h2x(hv.z, hv.w);
        *(uint2*)(Af + (size_t)w * H_DIM + lane * 4) = u;
    }

    const int o0 = off[w];
    const int n  = off[w + 1] - o0;

    float cb[N_BASES][4];
#pragma unroll
    for (int b = 0; b < N_BASES; b++)
#pragma unroll
        for (int c = 0; c < 4; c++) cb[b][c] = 0.f;

    const uint32_t wcbase = smem_u32(&wc[0][0]);

    for (int e = 0; e < n; e++) {
        uint32_t p = pay[o0 + e];
        int r = (int)(p >> 16);
        int s = (int)(p & 0xFFFFu);
        float4 v = *(const float4*)(h + (size_t)s * H_DIM + lane * 4);
        if (relu) {
            v.x = fmaxf(v.x, 0.f); v.y = fmaxf(v.y, 0.f);
            v.z = fmaxf(v.z, 0.f); v.w = fmaxf(v.w, 0.f);
        }
        float w0, w1, w2, w3, w4, w5, w6, w7;
        uint32_t wrow = wcbase + (uint32_t)r * (N_BASES * 4);
        asm("ld.shared.v4.f32 {%0,%1,%2,%3}, [%4];"
            : "=f"(w0), "=f"(w1), "=f"(w2), "=f"(w3) : "r"(wrow));
        asm("ld.shared.v4.f32 {%0,%1,%2,%3}, [%4];"
            : "=f"(w4), "=f"(w5), "=f"(w6), "=f"(w7) : "r"(wrow + 16));
        float wcv[8] = {w0, w1, w2, w3, w4, w5, w6, w7};
#pragma unroll
        for (int b = 0; b < N_BASES; b++) {
            float wcb = wcv[b];
            cb[b][0] = fmaf(wcb, v.x, cb[b][0]);
            cb[b][1] = fmaf(wcb, v.y, cb[b][1]);
            cb[b][2] = fmaf(wcb, v.z, cb[b][2]);
            cb[b][3] = fmaf(wcb, v.w, cb[b][3]);
        }
    }

#pragma unroll
    for (int b = 0; b < N_BASES; b++) {
        uint2 u;
        u.x = h2x(cb[b][0], cb[b][1]);
        u.y = h2x(cb[b][2], cb[b][3]);
        *(uint2*)(comp + ((size_t)b * N_ENT + w) * H_DIM + lane * 4) = u;
    }
}

// ---------------------------------------------------------------------------
// Prep W planes: g<8 -> basis[g] transposed [o][i]; g==8 -> loop_w transposed.
// fp16 hi + fp16 lo (lo lands in subnormals; preserved by fp16 MMA).
// ---------------------------------------------------------------------------
__global__ void prep_w_kernel(const float* __restrict__ basis,
                              const float* __restrict__ loop_w,
                              __half* __restrict__ Wt_hi,
                              __half* __restrict__ Wt_lo)
{
    int idx = blockIdx.x * blockDim.x + threadIdx.x;
    const int total = 9 * H_DIM * H_DIM;
    if (idx >= total) return;
    int g  = idx >> 14;
    int io = idx & 16383;                  // i*128 + o
    float s = (g < 8) ? basis[g * 16384 + io] : loop_w[io];
    int i = io >> 7, o = io & 127;
    size_t oidx = (size_t)g * 16384 + o * 128 + i;
    __half hi = __float2half_rn(s);
    __half lo = __float2half_rn(s - __half2float(hi));
    Wt_hi[oidx] = hi;
    Wt_lo[oidx] = lo;
}

// ---------------------------------------------------------------------------
// Single K=1152 GEMM: OUT = [comp_0..7 | Af] @ [[basis_0..7];[loop]] + bias.
// fp16 2-term: C = A*Wh + A*Wl.  CTA tile 128x128, 8 warps (4M x 2N),
// warp tile 32x64, fp32 acc across whole K.  3-stage cp.async ring,
// prefetch distance 2, wait_group 1, one barrier per stage.
// Optional fused ReLU on output (final layer).
// ---------------------------------------------------------------------------
#define PITCH9   144                    // 128B row + 16B pad
#define ST_A     0
#define ST_WH    18432
#define ST_WL    36864
#define STAGE_SZ 55296
#define GEMM_SMEM (3 * STAGE_SZ)        // 165888

__global__ __launch_bounds__(256, 1)
void gemm9_kernel(const __half* __restrict__ comp,
                  const __half* __restrict__ Af,
                  const __half* __restrict__ Wthi,
                  const __half* __restrict__ Wtlo,
                  const float* __restrict__ bias,
                  float* __restrict__ OUT,
                  int M, int relu)
{
    extern __shared__ char smem[];
    const uint32_t sb = smem_u32(smem);
    const int tid   = threadIdx.x;
    const int wid   = tid >> 5;
    const int lane  = tid & 31;
    const int wm    = wid >> 1;
    const int wn    = wid & 1;
    const int m0    = blockIdx.x * 128;

    const int q   = lane >> 3;
    const int r8  = lane & 7;
    const int arow_base = wm * 32 + r8 + (q & 1) * 8;
    const int acol_add  = (q >> 1) * 8;
    const int brow_base = wn * 64 + (q >> 1) * 8 + r8;
    const int bcol_add  = (q & 1) * 8;
    const int gr0 = m0 + wm * 32 + (lane >> 2);

#define PREFETCH(t)                                                           \
    do {                                                                      \
        const int _g = (t) >> 1, _hf = (t) & 1;                               \
        const __half* _a  = (_g < 8)                                          \
            ? comp + (size_t)_g * N_ENT * H_DIM : Af;                         \
        const __half* _wh = Wthi + _g * 16384;                                \
        const __half* _wl = Wtlo + _g * 16384;                                \
        const uint32_t _st = sb + ((t) % 3) * STAGE_SZ;                       \
        _Pragma("unroll")                                                     \
        for (int _i = 0; _i < 4; _i++) {                                      \
            int _idx = tid + _i * 256;      /* 0..1023 */                     \
            int _row = _idx >> 3;           /* 0..127 */                      \
            int _c8  = (_idx & 7) * 8;      /* fp16 col within 64 */          \
            uint32_t _sa = _st + _row * PITCH9 + _c8 * 2;                     \
            if (m0 + _row < M)                                                \
                CP_ASYNC16(_sa + ST_A,                                        \
                    _a + (size_t)(m0 + _row) * H_DIM + _hf * 64 + _c8);       \
            else                                                              \
                *(uint4*)(smem + (_sa + ST_A - sb)) = make_uint4(0,0,0,0);    \
            CP_ASYNC16(_sa + ST_WH,                                           \
                _wh + (size_t)_row * H_DIM + _hf * 64 + _c8);                 \
            CP_ASYNC16(_sa + ST_WL,                                           \
                _wl + (size_t)_row * H_DIM + _hf * 64 + _c8);                 \
        }                                                                     \
    } while (0)

    float acc[2][8][4];
#pragma unroll
    for (int mt = 0; mt < 2; mt++)
#pragma unroll
        for (int nt = 0; nt < 8; nt++)
#pragma unroll
            for (int c = 0; c < 4; c++) acc[mt][nt][c] = 0.f;

    PREFETCH(0);
    CP_COMMIT();
    PREFETCH(1);
    CP_COMMIT();

    for (int t = 0; t < 18; t++) {
        CP_WAIT1();
        __syncthreads();

        if (t + 2 < 18) PREFETCH(t + 2);
        CP_COMMIT();

        const uint32_t st = sb + (t % 3) * STAGE_SZ;

#pragma unroll
        for (int ks = 0; ks < 4; ks++) {
            const int k0 = ks * 16;
            uint32_t a[2][4], bh[8][2], bl[8][2];
#pragma unroll
            for (int mt = 0; mt < 2; mt++) {
                uint32_t off = (uint32_t)((arow_base + mt * 16) * PITCH9
                                          + (k0 + acol_add) * 2);
                LDMX4(a[mt][0], a[mt][1], a[mt][2], a[mt][3], st + ST_A + off);
            }
#pragma unroll
            for (int p = 0; p < 4; p++) {
                uint32_t off = (uint32_t)((brow_base + p * 16) * PITCH9
                                          + (k0 + bcol_add) * 2);
                LDMX4(bh[2 * p][0], bh[2 * p][1], bh[2 * p + 1][0],
                      bh[2 * p + 1][1], st + ST_WH + off);
                LDMX4(bl[2 * p][0], bl[2 * p][1], bl[2 * p + 1][0],
                      bl[2 * p + 1][1], st + ST_WL + off);
            }
#pragma unroll
            for (int mt = 0; mt < 2; mt++)
#pragma unroll
                for (int nt = 0; nt < 8; nt++) {
                    MMA_F16(acc[mt][nt], a[mt], bh[nt]);
                    MMA_F16(acc[mt][nt], a[mt], bl[nt]);
                }
        }
    }

    // ---- epilogue: OUT = acc + bias (optional ReLU) ----
#pragma unroll
    for (int mt = 0; mt < 2; mt++) {
        int row = gr0 + mt * 16;
#pragma unroll
        for (int nt = 0; nt < 8; nt++) {
            int col = wn * 64 + nt * 8 + (lane & 3) * 2;
            float2 bv = *(const float2*)(bias + col);
            float o0 = acc[mt][nt][0] + bv.x, o1 = acc[mt][nt][1] + bv.y;
            float o2 = acc[mt][nt][2] + bv.x, o3 = acc[mt][nt][3] + bv.y;
            if (relu) {
                o0 = fmaxf(o0, 0.f); o1 = fmaxf(o1, 0.f);
                o2 = fmaxf(o2, 0.f); o3 = fmaxf(o3, 0.f);
            }
            if (row < M)
                *(float2*)(OUT + (size_t)row * H_DIM + col) = make_float2(o0, o1);
            if (row + 8 < M)
                *(float2*)(OUT + (size_t)(row + 8) * H_DIM + col) = make_float2(o2, o3);
        }
    }
#undef PREFETCH
}

// ---------------------------------------------------------------------------
// Launch. agg1 is the 4th launch -> ncu-profiled.
// ---------------------------------------------------------------------------
extern "C" void kernel_launch(void* const* d_in, const int* in_sizes, int n_in,
                              void* d_out, int out_size)
{
    const float* entity_emb = (const float*)d_in[0];
    const float* basis1     = (const float*)d_in[1];
    const float* w_comp1    = (const float*)d_in[2];
    const float* loop_w1    = (const float*)d_in[3];
    const float* bias1      = (const float*)d_in[4];
    const float* basis2     = (const float*)d_in[5];
    const float* w_comp2    = (const float*)d_in[6];
    const float* loop_w2    = (const float*)d_in[7];
    const float* bias2      = (const float*)d_in[8];
    const int*   src        = (const int*)d_in[9];
    const int*   dst        = (const int*)d_in[10];
    const int*   rel        = (const int*)d_in[11];
    float*       out        = (float*)d_out;

    const int E = in_sizes[9];

    __half *dWth, *dWtl, *dAf, *dC;
    float *dH1;
    int *dcnt, *doff, *dcur;
    uint32_t *dpay;
    cudaGetSymbolAddress((void**)&dWth, g_Wt_hi);
    cudaGetSymbolAddress((void**)&dWtl, g_Wt_lo);
    cudaGetSymbolAddress((void**)&dAf,  g_Af);
    cudaGetSymbolAddress((void**)&dC,   g_comp);
    cudaGetSymbolAddress((void**)&dH1,  g_H1);
    cudaGetSymbolAddress((void**)&dcnt, g_cnt);
    cudaGetSymbolAddress((void**)&doff, g_off);
    cudaGetSymbolAddress((void**)&dcur, g_cur);
    cudaGetSymbolAddress((void**)&dpay, g_pay);

    cudaFuncSetAttribute(gemm9_kernel,
                         cudaFuncAttributeMaxDynamicSharedMemorySize, GEMM_SMEM);

    const int pw_blocks = (9 * H_DIM * H_DIM + 255) / 256;
    const int eg_blocks = (E + 255) / 256;
    const int gemm_grid = (N_ENT + 127) / 128;       // 391
    const int agg_blocks = (N_ENT * 32 + 255) / 256;

    // ---------------- binning (cnt pre-zeroed; scan re-zeroes) ----------------
    hist_kernel<<<eg_blocks, 256>>>(dst, dcnt, E);
    scan_kernel<<<1, 1024>>>(dcnt, doff, dcur);
    fill_kernel<<<eg_blocks, 256>>>(src, dst, rel, dcur, dpay, E);

    // ---------------- Layer 1 ----------------
    agg_kernel<<<agg_blocks, 256>>>(entity_emb, dpay, doff, w_comp1,
                                    dC, dAf, 0);               // profiled (#4)
    prep_w_kernel<<<pw_blocks, 256>>>(basis1, loop_w1, dWth, dWtl);
    gemm9_kernel<<<gemm_grid, 256, GEMM_SMEM>>>(dC, dAf, dWth, dWtl,
                                                bias1, dH1, N_ENT, 0);

    // ---------------- Layer 2 ----------------
    agg_kernel<<<agg_blocks, 256>>>(dH1, dpay, doff, w_comp2,
                                    dC, dAf, 1);               // fused ReLU
    prep_w_kernel<<<pw_blocks, 256>>>(basis2, loop_w2, dWth, dWtl);
    gemm9_kernel<<<gemm_grid, 256, GEMM_SMEM>>>(dC, dAf, dWth, dWtl,
                                                bias2, out, N_ENT, 1);  // ReLU
}